// round 4
// baseline (speedup 1.0000x reference)
#include <cuda_runtime.h>
#include <cstdint>

#define Nn 50000
#define Ee 800000
#define NEG 0.2f

// ---------------- scratch (device globals; no runtime allocation) ----------
__device__ float g_xl[(size_t)Nn * 128];
__device__ float g_xr[(size_t)Nn * 128];
__device__ float g_h[(size_t)Nn * 128];
__device__ float g_lsum[Nn];
__device__ float g_lattr[Nn];
__device__ int   g_cnt[Nn];
__device__ int   g_beg[Nn];
__device__ int   g_wp[Nn];
__device__ int   g_cursor;
__device__ int2  g_edge[Ee];          // (src, attr-bits) packed

// ---------------- helpers ---------------------------------------------------
__device__ __forceinline__ float lrelu(float v) { return (v > 0.f) ? v : NEG * v; }

__device__ __forceinline__ uint32_t to_tf32(float f) {
    uint32_t u;
    asm("cvt.rna.tf32.f32 %0, %1;" : "=r"(u) : "f"(f));
    return u;
}
__device__ __forceinline__ void cp16(void* s, const void* g, bool pred) {
    unsigned sa = (unsigned)__cvta_generic_to_shared(s);
    int sz = pred ? 16 : 0;
    asm volatile("cp.async.cg.shared.global [%0], [%1], 16, %2;\n"
                 :: "r"(sa), "l"(g), "r"(sz));
}
__device__ __forceinline__ void cp_commit() { asm volatile("cp.async.commit_group;\n"); }
__device__ __forceinline__ void cp_wait()   { asm volatile("cp.async.wait_group 0;\n"); }

__device__ __forceinline__ void mma_tf32(float c[4], uint32_t a0, uint32_t a1,
                                         uint32_t a2, uint32_t a3,
                                         uint32_t b0, uint32_t b1) {
    asm volatile(
        "mma.sync.aligned.m16n8k8.row.col.f32.tf32.tf32.f32 "
        "{%0,%1,%2,%3}, {%4,%5,%6,%7}, {%8,%9}, {%0,%1,%2,%3};\n"
        : "+f"(c[0]), "+f"(c[1]), "+f"(c[2]), "+f"(c[3])
        : "r"(a0), "r"(a1), "r"(a2), "r"(a3), "r"(b0), "r"(b1));
}

// ================= CSR build (order-free segment allocation) ================
__global__ void hist_k(const int* __restrict__ ei, const float* __restrict__ ea) {
    int e = blockIdx.x * blockDim.x + threadIdx.x;
    if (e < Ee) {
        int dst = ei[Ee + e];
        atomicAdd(&g_cnt[dst], 1);
        atomicAdd(&g_lsum[dst], ea[e]);
    }
}
__global__ void alloc_k() {
    int n = blockIdx.x * blockDim.x + threadIdx.x;
    if (n >= Nn) return;
    int c = g_cnt[n];
    int beg = atomicAdd(&g_cursor, c);
    g_beg[n] = beg;
    g_wp[n] = beg;
    g_lattr[n] = (c > 0) ? g_lsum[n] / (float)c : 0.f;
}
__global__ void scatter_k(const int* __restrict__ ei, const float* __restrict__ ea) {
    int e = blockIdx.x * blockDim.x + threadIdx.x;
    if (e < Ee) {
        int dst = ei[Ee + e];
        int pos = atomicAdd(&g_wp[dst], 1);
        g_edge[pos] = make_int2(ei[e], __float_as_int(ea[e]));
    }
}

// ================= tf32 tensor-core GEMM ====================================
#define ASTRIDE 36
#define BSTRIDE 136
#define ASZ (128 * ASTRIDE)
#define BSZ (32 * BSTRIDE)
#define GEMM_SMEM ((ASZ + BSZ) * 2 * 4)

__global__ void __launch_bounds__(256, 2)
gemm_tc_k(const float* __restrict__ A,
          const float* __restrict__ W0, const float* __restrict__ b0, float* __restrict__ C0,
          const float* __restrict__ W1, const float* __restrict__ b1, float* __restrict__ C1,
          int M, int relu) {
    const float* W    = blockIdx.y ? W1 : W0;
    const float* bias = blockIdx.y ? b1 : b0;
    float*       Cm   = blockIdx.y ? C1 : C0;

    extern __shared__ float sm[];
    float* As[2] = { sm, sm + ASZ };
    float* Bs[2] = { sm + 2 * ASZ, sm + 2 * ASZ + BSZ };

    const int t = threadIdx.x;
    const int lane = t & 31;
    const int wid = t >> 5;
    const int warp_m = wid & 3;
    const int warp_n = wid >> 2;
    const int row0 = blockIdx.x * 128;

    const int a_row = t >> 1;
    const int a_colb = (t & 1) * 16;
    const int b_k = t >> 3;
    const int b_nb = (t & 7) * 16;
    const bool a_ok = (row0 + a_row) < M;
    const float* Arow = A + (size_t)(row0 + a_row) * 128;

    float acc[2][8][4];
#pragma unroll
    for (int i = 0; i < 2; i++)
#pragma unroll
        for (int j = 0; j < 8; j++)
#pragma unroll
            for (int k = 0; k < 4; k++) acc[i][j][k] = 0.f;

#pragma unroll
    for (int q = 0; q < 4; q++) {
        cp16(&As[0][a_row * ASTRIDE + a_colb + q * 4], Arow + a_colb + q * 4, a_ok);
        cp16(&Bs[0][b_k * BSTRIDE + b_nb + q * 4], W + (size_t)b_k * 128 + b_nb + q * 4, true);
    }
    cp_commit();

    int buf = 0;
    for (int c = 0; c < 4; c++) {
        cp_wait();
        __syncthreads();
        if (c < 3) {
            int k0 = (c + 1) * 32;
            int nb = buf ^ 1;
#pragma unroll
            for (int q = 0; q < 4; q++) {
                cp16(&As[nb][a_row * ASTRIDE + a_colb + q * 4], Arow + k0 + a_colb + q * 4, a_ok);
                cp16(&Bs[nb][b_k * BSTRIDE + b_nb + q * 4], W + (size_t)(k0 + b_k) * 128 + b_nb + q * 4, true);
            }
            cp_commit();
        }
        const float* as = As[buf];
        const float* bs = Bs[buf];
        const int ar = warp_m * 32 + (lane >> 2);
        const int ac = lane & 3;
        const int bn = warp_n * 64 + (lane >> 2);
        const int bk = lane & 3;
#pragma unroll
        for (int ks = 0; ks < 4; ks++) {
            uint32_t af[2][4];
#pragma unroll
            for (int mt = 0; mt < 2; mt++) {
                const float* ap = as + (ar + mt * 16) * ASTRIDE + ks * 8 + ac;
                af[mt][0] = to_tf32(ap[0]);
                af[mt][1] = to_tf32(ap[8 * ASTRIDE]);
                af[mt][2] = to_tf32(ap[4]);
                af[mt][3] = to_tf32(ap[8 * ASTRIDE + 4]);
            }
#pragma unroll
            for (int nt = 0; nt < 8; nt++) {
                const float* bp = bs + (ks * 8 + bk) * BSTRIDE + bn + nt * 8;
                uint32_t bf0 = to_tf32(bp[0]);
                uint32_t bf1 = to_tf32(bp[4 * BSTRIDE]);
                mma_tf32(acc[0][nt], af[0][0], af[0][1], af[0][2], af[0][3], bf0, bf1);
                mma_tf32(acc[1][nt], af[1][0], af[1][1], af[1][2], af[1][3], bf0, bf1);
            }
        }
        __syncthreads();
        buf ^= 1;
    }

    const int crow = row0 + warp_m * 32 + (lane >> 2);
    const int ccol0 = warp_n * 64 + (lane & 3) * 2;
#pragma unroll
    for (int nt = 0; nt < 8; nt++) {
        int col = ccol0 + nt * 8;
        float bx = bias[col], by = bias[col + 1];
#pragma unroll
        for (int mt = 0; mt < 2; mt++) {
            int r0 = crow + mt * 16;
            float v0 = acc[mt][nt][0] + bx, v1 = acc[mt][nt][1] + by;
            float v2 = acc[mt][nt][2] + bx, v3 = acc[mt][nt][3] + by;
            if (relu) {
                v0 = fmaxf(v0, 0.f); v1 = fmaxf(v1, 0.f);
                v2 = fmaxf(v2, 0.f); v3 = fmaxf(v3, 0.f);
            }
            if (r0 < M)     *(float2*)(Cm + (size_t)r0 * 128 + col)       = make_float2(v0, v1);
            if (r0 + 8 < M) *(float2*)(Cm + (size_t)(r0 + 8) * 128 + col) = make_float2(v2, v3);
        }
    }
}

// ================= per-node fused GAT layer (4-way unrolled) ================
struct EdgeAcc {
    float4 acc;
    float  ssum;
};

__device__ __forceinline__ float edge_logit(float4 a, float4 br, float attr,
                                            float4 w4, float4 at4) {
    float m0 = lrelu(a.x + br.x + attr * w4.x);
    float m1 = lrelu(a.y + br.y + attr * w4.y);
    float m2 = lrelu(a.z + br.z + attr * w4.z);
    float m3 = lrelu(a.w + br.w + attr * w4.w);
    return m0 * at4.x + m1 * at4.y + m2 * at4.z + m3 * at4.w;
}
__device__ __forceinline__ void edge_apply(EdgeAcc& s, float e, float4 a) {
    s.acc.x = fmaf(e, a.x, s.acc.x);
    s.acc.y = fmaf(e, a.y, s.acc.y);
    s.acc.z = fmaf(e, a.z, s.acc.z);
    s.acc.w = fmaf(e, a.w, s.acc.w);
    s.ssum += e;
}

__global__ void __launch_bounds__(256)
node_agg_k(const float* __restrict__ We, const float* __restrict__ att,
           const float* __restrict__ bo) {
    int n = (blockIdx.x * blockDim.x + threadIdx.x) >> 5;
    int lane = threadIdx.x & 31;
    if (n >= Nn) return;

    float4 br  = *(const float4*)(g_xr + (size_t)n * 128 + lane * 4);
    float4 w4  = *(const float4*)(We + lane * 4);
    float4 at4 = *(const float4*)(att + lane * 4);

    EdgeAcc s; s.acc = make_float4(0.f, 0.f, 0.f, 0.f); s.ssum = 0.f;

    const int beg = g_beg[n];
    const int end = beg + g_cnt[n];

    // self loop (not stored in edge array)
    {
        float4 a = *(const float4*)(g_xl + (size_t)n * 128 + lane * 4);
        float p = edge_logit(a, br, g_lattr[n], w4, at4);
        p += __shfl_xor_sync(0xFFFFFFFFu, p, 1);
        p += __shfl_xor_sync(0xFFFFFFFFu, p, 2);
        p += __shfl_xor_sync(0xFFFFFFFFu, p, 4);
        edge_apply(s, __expf(p), a);
    }

    int j = beg;
    for (; j + 4 <= end; j += 4) {
        int2 e0 = g_edge[j], e1 = g_edge[j + 1], e2 = g_edge[j + 2], e3 = g_edge[j + 3];
        float4 a0 = *(const float4*)(g_xl + (size_t)e0.x * 128 + lane * 4);
        float4 a1 = *(const float4*)(g_xl + (size_t)e1.x * 128 + lane * 4);
        float4 a2 = *(const float4*)(g_xl + (size_t)e2.x * 128 + lane * 4);
        float4 a3 = *(const float4*)(g_xl + (size_t)e3.x * 128 + lane * 4);
        float p0 = edge_logit(a0, br, __int_as_float(e0.y), w4, at4);
        float p1 = edge_logit(a1, br, __int_as_float(e1.y), w4, at4);
        float p2 = edge_logit(a2, br, __int_as_float(e2.y), w4, at4);
        float p3 = edge_logit(a3, br, __int_as_float(e3.y), w4, at4);
        p0 += __shfl_xor_sync(0xFFFFFFFFu, p0, 1);
        p1 += __shfl_xor_sync(0xFFFFFFFFu, p1, 1);
        p2 += __shfl_xor_sync(0xFFFFFFFFu, p2, 1);
        p3 += __shfl_xor_sync(0xFFFFFFFFu, p3, 1);
        p0 += __shfl_xor_sync(0xFFFFFFFFu, p0, 2);
        p1 += __shfl_xor_sync(0xFFFFFFFFu, p1, 2);
        p2 += __shfl_xor_sync(0xFFFFFFFFu, p2, 2);
        p3 += __shfl_xor_sync(0xFFFFFFFFu, p3, 2);
        p0 += __shfl_xor_sync(0xFFFFFFFFu, p0, 4);
        p1 += __shfl_xor_sync(0xFFFFFFFFu, p1, 4);
        p2 += __shfl_xor_sync(0xFFFFFFFFu, p2, 4);
        p3 += __shfl_xor_sync(0xFFFFFFFFu, p3, 4);
        edge_apply(s, __expf(p0), a0);
        edge_apply(s, __expf(p1), a1);
        edge_apply(s, __expf(p2), a2);
        edge_apply(s, __expf(p3), a3);
    }
    for (; j < end; j++) {
        int2 e0 = g_edge[j];
        float4 a0 = *(const float4*)(g_xl + (size_t)e0.x * 128 + lane * 4);
        float p0 = edge_logit(a0, br, __int_as_float(e0.y), w4, at4);
        p0 += __shfl_xor_sync(0xFFFFFFFFu, p0, 1);
        p0 += __shfl_xor_sync(0xFFFFFFFFu, p0, 2);
        p0 += __shfl_xor_sync(0xFFFFFFFFu, p0, 4);
        edge_apply(s, __expf(p0), a0);
    }

    float inv = 1.f / (s.ssum + 1e-16f);
    float4 bo4 = *(const float4*)(bo + lane * 4);
    float4 o;
    o.x = fmaxf(s.acc.x * inv + bo4.x, 0.f);
    o.y = fmaxf(s.acc.y * inv + bo4.y, 0.f);
    o.z = fmaxf(s.acc.z * inv + bo4.z, 0.f);
    o.w = fmaxf(s.acc.w * inv + bo4.w, 0.f);
    *(float4*)(g_h + (size_t)n * 128 + lane * 4) = o;
}

// ================= launch ===================================================
extern "C" void kernel_launch(void* const* d_in, const int* in_sizes, int n_in,
                              void* d_out, int out_size) {
    const float* x    = (const float*)d_in[0];
    const int*   ei   = (const int*)  d_in[1];
    const float* ea   = (const float*)d_in[2];
    const float* Wl1  = (const float*)d_in[3];
    const float* bl1  = (const float*)d_in[4];
    const float* Wr1  = (const float*)d_in[5];
    const float* br1  = (const float*)d_in[6];
    const float* We1  = (const float*)d_in[7];
    const float* att1 = (const float*)d_in[8];
    const float* bo1  = (const float*)d_in[9];
    const float* Wl2  = (const float*)d_in[10];
    const float* bl2  = (const float*)d_in[11];
    const float* Wr2  = (const float*)d_in[12];
    const float* br2  = (const float*)d_in[13];
    const float* We2  = (const float*)d_in[14];
    const float* att2 = (const float*)d_in[15];
    const float* bo2  = (const float*)d_in[16];
    const float* Wlin = (const float*)d_in[17];
    const float* blin = (const float*)d_in[18];
    float* out = (float*)d_out;

    float *pxl, *pxr, *ph;
    void *pcnt, *plsum, *pcur;
    cudaGetSymbolAddress((void**)&pxl, g_xl);
    cudaGetSymbolAddress((void**)&pxr, g_xr);
    cudaGetSymbolAddress((void**)&ph,  g_h);
    cudaGetSymbolAddress(&pcnt,  g_cnt);
    cudaGetSymbolAddress(&plsum, g_lsum);
    cudaGetSymbolAddress(&pcur,  g_cursor);

    static int smem_set = 0;
    if (!smem_set) {
        cudaFuncSetAttribute(gemm_tc_k, cudaFuncAttributeMaxDynamicSharedMemorySize, GEMM_SMEM);
        smem_set = 1;
    }

    const int TB = 256;
    const int gb_n  = (Nn + TB - 1) / TB;
    const int gb_e  = (Ee + TB - 1) / TB;
    const int gb_gemm = (Nn + 127) / 128;
    const int gb_node = (Nn * 32 + TB - 1) / TB;
    dim3 grid2(gb_gemm, 2), grid1(gb_gemm, 1);

    // ---- CSR build (order-free) ----
    cudaMemsetAsync(pcnt,  0, Nn * sizeof(int));
    cudaMemsetAsync(plsum, 0, Nn * sizeof(float));
    cudaMemsetAsync(pcur,  0, sizeof(int));
    hist_k<<<gb_e, TB>>>(ei, ea);
    alloc_k<<<gb_n, TB>>>();
    scatter_k<<<gb_e, TB>>>(ei, ea);

    // ---- layer 1 ----
    gemm_tc_k<<<grid2, TB, GEMM_SMEM>>>(x, Wl1, bl1, pxl, Wr1, br1, pxr, Nn, 0);
    node_agg_k<<<gb_node, TB>>>(We1, att1, bo1);

    // ---- layer 2 ----
    gemm_tc_k<<<grid2, TB, GEMM_SMEM>>>(ph, Wl2, bl2, pxl, Wr2, br2, pxr, Nn, 0);
    node_agg_k<<<gb_node, TB>>>(We2, att2, bo2);

    // ---- final linear + relu -> d_out ----
    gemm_tc_k<<<grid1, TB, GEMM_SMEM>>>(ph, Wlin, blin, out, Wlin, blin, out, Nn, 1);
}

// round 5
// speedup vs baseline: 1.0212x; 1.0212x over previous
#include <cuda_runtime.h>
#include <cstdint>

#define Nn 50000
#define Ee 800000
#define NEG 0.2f

// ---------------- scratch (device globals; no runtime allocation) ----------
__device__ float    g_xl[(size_t)Nn * 128];
__device__ float    g_xr[(size_t)Nn * 128];
__device__ float    g_h[(size_t)Nn * 128];
__device__ float    g_lsum[Nn];
__device__ float    g_lattr[Nn];
__device__ int      g_cnt[Nn];
__device__ int      g_beg[Nn];
__device__ int      g_wp[Nn];
__device__ int      g_cursor;
__device__ int2     g_edge[Ee];            // (src, attr-bits)
__device__ uint32_t g_wtf[5 * 128 * 128];  // weights pre-converted to tf32 bits

// ---------------- helpers ---------------------------------------------------
__device__ __forceinline__ float lrelu(float v) { return (v > 0.f) ? v : NEG * v; }

__device__ __forceinline__ uint32_t to_tf32(float f) {
    uint32_t u;
    asm("cvt.rna.tf32.f32 %0, %1;" : "=r"(u) : "f"(f));
    return u;
}
__device__ __forceinline__ void cp16(void* s, const void* g, bool pred) {
    unsigned sa = (unsigned)__cvta_generic_to_shared(s);
    int sz = pred ? 16 : 0;
    asm volatile("cp.async.cg.shared.global [%0], [%1], 16, %2;\n"
                 :: "r"(sa), "l"(g), "r"(sz));
}
__device__ __forceinline__ void cp_commit() { asm volatile("cp.async.commit_group;\n"); }
__device__ __forceinline__ void cp_wait()   { asm volatile("cp.async.wait_group 0;\n"); }

__device__ __forceinline__ void mma_tf32(float c[4], uint32_t a0, uint32_t a1,
                                         uint32_t a2, uint32_t a3,
                                         uint32_t b0, uint32_t b1) {
    asm volatile(
        "mma.sync.aligned.m16n8k8.row.col.f32.tf32.tf32.f32 "
        "{%0,%1,%2,%3}, {%4,%5,%6,%7}, {%8,%9}, {%0,%1,%2,%3};\n"
        : "+f"(c[0]), "+f"(c[1]), "+f"(c[2]), "+f"(c[3])
        : "r"(a0), "r"(a1), "r"(a2), "r"(a3), "r"(b0), "r"(b1));
}

// ================= weight preconvert (once per launch) ======================
__global__ void cvtW_k(const float* __restrict__ w0, const float* __restrict__ w1,
                       const float* __restrict__ w2, const float* __restrict__ w3,
                       const float* __restrict__ w4) {
    int i = blockIdx.x * blockDim.x + threadIdx.x;
    if (i >= 5 * 16384) return;
    int slot = i >> 14, off = i & 16383;
    const float* s = (slot == 0) ? w0 : (slot == 1) ? w1 : (slot == 2) ? w2
                   : (slot == 3) ? w3 : w4;
    g_wtf[i] = to_tf32(s[off]);
}

// ================= CSR build (order-free, warp-aggregated cursor) ===========
__global__ void hist_k(const int* __restrict__ ei, const float* __restrict__ ea) {
    int e = blockIdx.x * blockDim.x + threadIdx.x;
    if (e < Ee) {
        int dst = ei[Ee + e];
        atomicAdd(&g_cnt[dst], 1);
        atomicAdd(&g_lsum[dst], ea[e]);
    }
}
__global__ void alloc_k() {
    int n = blockIdx.x * blockDim.x + threadIdx.x;
    int lane = threadIdx.x & 31;
    int c = (n < Nn) ? g_cnt[n] : 0;
    int s = c;
#pragma unroll
    for (int off = 1; off < 32; off <<= 1) {
        int v = __shfl_up_sync(0xFFFFFFFFu, s, off);
        if (lane >= off) s += v;
    }
    int total = __shfl_sync(0xFFFFFFFFu, s, 31);
    int base = 0;
    if (lane == 31) base = atomicAdd(&g_cursor, total);
    base = __shfl_sync(0xFFFFFFFFu, base, 31);
    if (n < Nn) {
        int beg = base + s - c;
        g_beg[n] = beg;
        g_wp[n] = beg;
        g_lattr[n] = (c > 0) ? g_lsum[n] / (float)c : 0.f;
    }
}
__global__ void scatter_k(const int* __restrict__ ei, const float* __restrict__ ea) {
    int e = blockIdx.x * blockDim.x + threadIdx.x;
    if (e < Ee) {
        int dst = ei[Ee + e];
        int pos = atomicAdd(&g_wp[dst], 1);
        g_edge[pos] = make_int2(ei[e], __float_as_int(ea[e]));
    }
}

// ================= tf32 tensor-core GEMM ====================================
// B smem already holds tf32 bits (from g_wtf). A needs cvt only when cvtA!=0
// (layer-1 raw x); h is stored pre-rounded so layers 2/3 pass bits through.
#define ASTRIDE 36
#define BSTRIDE 136
#define ASZ (128 * ASTRIDE)
#define BSZ (32 * BSTRIDE)
#define GEMM_SMEM ((ASZ + BSZ) * 2 * 4)

__global__ void __launch_bounds__(256, 2)
gemm_tc_k(const float* __restrict__ A,
          const uint32_t* __restrict__ W0, const float* __restrict__ b0, float* __restrict__ C0,
          const uint32_t* __restrict__ W1, const float* __restrict__ b1, float* __restrict__ C1,
          int M, int relu, int cvtA) {
    const uint32_t* W  = blockIdx.y ? W1 : W0;
    const float* bias  = blockIdx.y ? b1 : b0;
    float*       Cm    = blockIdx.y ? C1 : C0;

    extern __shared__ float sm[];
    float*    As[2] = { sm, sm + ASZ };
    uint32_t* Bs[2] = { (uint32_t*)(sm + 2 * ASZ), (uint32_t*)(sm + 2 * ASZ + BSZ) };

    const int t = threadIdx.x;
    const int lane = t & 31;
    const int wid = t >> 5;
    const int warp_m = wid & 3;
    const int warp_n = wid >> 2;
    const int row0 = blockIdx.x * 128;

    const int a_row = t >> 1;
    const int a_colb = (t & 1) * 16;
    const int b_k = t >> 3;
    const int b_nb = (t & 7) * 16;
    const bool a_ok = (row0 + a_row) < M;
    const float* Arow = A + (size_t)(row0 + a_row) * 128;

    float acc[2][8][4];
#pragma unroll
    for (int i = 0; i < 2; i++)
#pragma unroll
        for (int j = 0; j < 8; j++)
#pragma unroll
            for (int k = 0; k < 4; k++) acc[i][j][k] = 0.f;

#pragma unroll
    for (int q = 0; q < 4; q++) {
        cp16(&As[0][a_row * ASTRIDE + a_colb + q * 4], Arow + a_colb + q * 4, a_ok);
        cp16(&Bs[0][b_k * BSTRIDE + b_nb + q * 4], W + (size_t)b_k * 128 + b_nb + q * 4, true);
    }
    cp_commit();

    int buf = 0;
    for (int c = 0; c < 4; c++) {
        cp_wait();
        __syncthreads();
        if (c < 3) {
            int k0 = (c + 1) * 32;
            int nb = buf ^ 1;
#pragma unroll
            for (int q = 0; q < 4; q++) {
                cp16(&As[nb][a_row * ASTRIDE + a_colb + q * 4], Arow + k0 + a_colb + q * 4, a_ok);
                cp16(&Bs[nb][b_k * BSTRIDE + b_nb + q * 4], W + (size_t)(k0 + b_k) * 128 + b_nb + q * 4, true);
            }
            cp_commit();
        }
        const uint32_t* as = (const uint32_t*)As[buf];
        const uint32_t* bs = Bs[buf];
        const int ar = warp_m * 32 + (lane >> 2);
        const int ac = lane & 3;
        const int bn = warp_n * 64 + (lane >> 2);
        const int bk = lane & 3;
#pragma unroll
        for (int ks = 0; ks < 4; ks++) {
            uint32_t af[2][4];
#pragma unroll
            for (int mt = 0; mt < 2; mt++) {
                const uint32_t* ap = as + (ar + mt * 16) * ASTRIDE + ks * 8 + ac;
                uint32_t r0 = ap[0];
                uint32_t r1 = ap[8 * ASTRIDE];
                uint32_t r2 = ap[4];
                uint32_t r3 = ap[8 * ASTRIDE + 4];
                if (cvtA) {
                    r0 = to_tf32(__uint_as_float(r0));
                    r1 = to_tf32(__uint_as_float(r1));
                    r2 = to_tf32(__uint_as_float(r2));
                    r3 = to_tf32(__uint_as_float(r3));
                }
                af[mt][0] = r0; af[mt][1] = r1; af[mt][2] = r2; af[mt][3] = r3;
            }
#pragma unroll
            for (int nt = 0; nt < 8; nt++) {
                const uint32_t* bp = bs + (ks * 8 + bk) * BSTRIDE + bn + nt * 8;
                uint32_t bf0 = bp[0];
                uint32_t bf1 = bp[4 * BSTRIDE];
                mma_tf32(acc[0][nt], af[0][0], af[0][1], af[0][2], af[0][3], bf0, bf1);
                mma_tf32(acc[1][nt], af[1][0], af[1][1], af[1][2], af[1][3], bf0, bf1);
            }
        }
        __syncthreads();
        buf ^= 1;
    }

    const int crow = row0 + warp_m * 32 + (lane >> 2);
    const int ccol0 = warp_n * 64 + (lane & 3) * 2;
#pragma unroll
    for (int nt = 0; nt < 8; nt++) {
        int col = ccol0 + nt * 8;
        float bx = bias[col], by = bias[col + 1];
#pragma unroll
        for (int mt = 0; mt < 2; mt++) {
            int r0 = crow + mt * 16;
            float v0 = acc[mt][nt][0] + bx, v1 = acc[mt][nt][1] + by;
            float v2 = acc[mt][nt][2] + bx, v3 = acc[mt][nt][3] + by;
            if (relu) {
                v0 = fmaxf(v0, 0.f); v1 = fmaxf(v1, 0.f);
                v2 = fmaxf(v2, 0.f); v3 = fmaxf(v3, 0.f);
            }
            if (r0 < M)     *(float2*)(Cm + (size_t)r0 * 128 + col)       = make_float2(v0, v1);
            if (r0 + 8 < M) *(float2*)(Cm + (size_t)(r0 + 8) * 128 + col) = make_float2(v2, v3);
        }
    }
}

// ================= per-node fused GAT layer =================================
// One warp per dst node. Output h pre-rounded to tf32 (bit-identical to what
// the downstream GEMM would produce; h is consumed ONLY by tf32 GEMMs).
__global__ void __launch_bounds__(256)
node_agg_k(const float* __restrict__ We, const float* __restrict__ att,
           const float* __restrict__ bo) {
    int n = (blockIdx.x * blockDim.x + threadIdx.x) >> 5;
    int lane = threadIdx.x & 31;
    if (n >= Nn) return;

    float4 br  = *(const float4*)(g_xr + (size_t)n * 128 + lane * 4);
    float4 w4  = *(const float4*)(We + lane * 4);
    float4 at4 = *(const float4*)(att + lane * 4);

    float4 acc = make_float4(0.f, 0.f, 0.f, 0.f);
    float ssum = 0.f;

    const int beg = g_beg[n];
    const int end = beg + g_cnt[n];

    // self loop (kept out of the edge array)
    {
        float4 a = *(const float4*)(g_xl + (size_t)n * 128 + lane * 4);
        float attr = g_lattr[n];
        float m0 = lrelu(a.x + br.x + attr * w4.x);
        float m1 = lrelu(a.y + br.y + attr * w4.y);
        float m2 = lrelu(a.z + br.z + attr * w4.z);
        float m3 = lrelu(a.w + br.w + attr * w4.w);
        float p = m0 * at4.x + m1 * at4.y + m2 * at4.z + m3 * at4.w;
        p += __shfl_xor_sync(0xFFFFFFFFu, p, 1);
        p += __shfl_xor_sync(0xFFFFFFFFu, p, 2);
        p += __shfl_xor_sync(0xFFFFFFFFu, p, 4);
        float e = __expf(p);
        acc.x = fmaf(e, a.x, acc.x);
        acc.y = fmaf(e, a.y, acc.y);
        acc.z = fmaf(e, a.z, acc.z);
        acc.w = fmaf(e, a.w, acc.w);
        ssum += e;
    }

    for (int j = beg; j < end; j++) {
        int2 ed = g_edge[j];
        float attr = __int_as_float(ed.y);
        float4 a = *(const float4*)(g_xl + (size_t)ed.x * 128 + lane * 4);
        float m0 = lrelu(a.x + br.x + attr * w4.x);
        float m1 = lrelu(a.y + br.y + attr * w4.y);
        float m2 = lrelu(a.z + br.z + attr * w4.z);
        float m3 = lrelu(a.w + br.w + attr * w4.w);
        float p = m0 * at4.x + m1 * at4.y + m2 * at4.z + m3 * at4.w;
        p += __shfl_xor_sync(0xFFFFFFFFu, p, 1);
        p += __shfl_xor_sync(0xFFFFFFFFu, p, 2);
        p += __shfl_xor_sync(0xFFFFFFFFu, p, 4);
        float e = __expf(p);
        acc.x = fmaf(e, a.x, acc.x);
        acc.y = fmaf(e, a.y, acc.y);
        acc.z = fmaf(e, a.z, acc.z);
        acc.w = fmaf(e, a.w, acc.w);
        ssum += e;
    }

    float inv = 1.f / (ssum + 1e-16f);
    float4 bo4 = *(const float4*)(bo + lane * 4);
    uint4 o;
    o.x = to_tf32(fmaxf(acc.x * inv + bo4.x, 0.f));
    o.y = to_tf32(fmaxf(acc.y * inv + bo4.y, 0.f));
    o.z = to_tf32(fmaxf(acc.z * inv + bo4.z, 0.f));
    o.w = to_tf32(fmaxf(acc.w * inv + bo4.w, 0.f));
    *(uint4*)(g_h + (size_t)n * 128 + lane * 4) = o;
}

// ================= launch ===================================================
extern "C" void kernel_launch(void* const* d_in, const int* in_sizes, int n_in,
                              void* d_out, int out_size) {
    const float* x    = (const float*)d_in[0];
    const int*   ei   = (const int*)  d_in[1];
    const float* ea   = (const float*)d_in[2];
    const float* Wl1  = (const float*)d_in[3];
    const float* bl1  = (const float*)d_in[4];
    const float* Wr1  = (const float*)d_in[5];
    const float* br1  = (const float*)d_in[6];
    const float* We1  = (const float*)d_in[7];
    const float* att1 = (const float*)d_in[8];
    const float* bo1  = (const float*)d_in[9];
    const float* Wl2  = (const float*)d_in[10];
    const float* bl2  = (const float*)d_in[11];
    const float* Wr2  = (const float*)d_in[12];
    const float* br2  = (const float*)d_in[13];
    const float* We2  = (const float*)d_in[14];
    const float* att2 = (const float*)d_in[15];
    const float* bo2  = (const float*)d_in[16];
    const float* Wlin = (const float*)d_in[17];
    const float* blin = (const float*)d_in[18];
    float* out = (float*)d_out;

    float *pxl, *pxr, *ph;
    uint32_t* pw;
    void *pcnt, *plsum, *pcur;
    cudaGetSymbolAddress((void**)&pxl, g_xl);
    cudaGetSymbolAddress((void**)&pxr, g_xr);
    cudaGetSymbolAddress((void**)&ph,  g_h);
    cudaGetSymbolAddress((void**)&pw,  g_wtf);
    cudaGetSymbolAddress(&pcnt,  g_cnt);
    cudaGetSymbolAddress(&plsum, g_lsum);
    cudaGetSymbolAddress(&pcur,  g_cursor);

    static int smem_set = 0;
    if (!smem_set) {
        cudaFuncSetAttribute(gemm_tc_k, cudaFuncAttributeMaxDynamicSharedMemorySize, GEMM_SMEM);
        smem_set = 1;
    }

    const int TB = 256;
    const int gb_n  = (Nn + TB - 1) / TB;
    const int gb_e  = (Ee + TB - 1) / TB;
    const int gb_w  = (5 * 16384 + TB - 1) / TB;
    const int gb_gemm = (Nn + 127) / 128;
    const int gb_node = (Nn * 32 + TB - 1) / TB;
    dim3 grid2(gb_gemm, 2), grid1(gb_gemm, 1);

    const uint32_t* wl1 = pw + 0 * 16384;
    const uint32_t* wr1 = pw + 1 * 16384;
    const uint32_t* wl2 = pw + 2 * 16384;
    const uint32_t* wr2 = pw + 3 * 16384;
    const uint32_t* wli = pw + 4 * 16384;

    // ---- CSR build + weight preconvert ----
    cudaMemsetAsync(pcnt,  0, Nn * sizeof(int));
    cudaMemsetAsync(plsum, 0, Nn * sizeof(float));
    cudaMemsetAsync(pcur,  0, sizeof(int));
    cvtW_k<<<gb_w, TB>>>(Wl1, Wr1, Wl2, Wr2, Wlin);
    hist_k<<<gb_e, TB>>>(ei, ea);
    alloc_k<<<gb_n, TB>>>();
    scatter_k<<<gb_e, TB>>>(ei, ea);

    // ---- layer 1 (A = raw x -> cvtA=1) ----
    gemm_tc_k<<<grid2, TB, GEMM_SMEM>>>(x, wl1, bl1, pxl, wr1, br1, pxr, Nn, 0, 1);
    node_agg_k<<<gb_node, TB>>>(We1, att1, bo1);

    // ---- layer 2 (A = pre-rounded h -> cvtA=0) ----
    gemm_tc_k<<<grid2, TB, GEMM_SMEM>>>(ph, wl2, bl2, pxl, wr2, br2, pxr, Nn, 0, 0);
    node_agg_k<<<gb_node, TB>>>(We2, att2, bo2);

    // ---- final linear + relu -> d_out ----
    gemm_tc_k<<<grid1, TB, GEMM_SMEM>>>(ph, wli, blin, out, wli, blin, out, Nn, 1, 0);
}